// round 1
// baseline (speedup 1.0000x reference)
#include <cuda_runtime.h>

#define B_ 16
#define D_ 512
#define N_ 4096
#define K_ 64
#define EPSV 1e-12f

// ---- scratch (static device globals; no runtime allocation) ----
__device__ float g_S[B_ * K_ * N_];        // softmax weights (16 MB)
__device__ float g_Vp0[B_ * K_ * D_];      // GEMM2 partial, n-split 0
__device__ float g_Vp1[B_ * K_ * D_];      // GEMM2 partial, n-split 1
__device__ float g_wsum[B_ * K_];
__device__ float g_rn[B_ * K_];            // per-row norm^2 after intra-normalize
__device__ float g_sumsq[B_];

// ---- packed f32x2 helpers (FFMA2: full-rate fp32 on sm_103a) ----
__device__ __forceinline__ unsigned long long fma2(unsigned long long a,
                                                   unsigned long long b,
                                                   unsigned long long c) {
    unsigned long long r;
    asm("fma.rn.f32x2 %0, %1, %2, %3;" : "=l"(r) : "l"(a), "l"(b), "l"(c));
    return r;
}
__device__ __forceinline__ unsigned long long add2(unsigned long long a,
                                                   unsigned long long b) {
    unsigned long long r;
    asm("add.rn.f32x2 %0, %1, %2;" : "=l"(r) : "l"(a), "l"(b));
    return r;
}
__device__ __forceinline__ unsigned long long pack2(float lo, float hi) {
    unsigned long long r;
    asm("mov.b64 %0, {%1, %2};" : "=l"(r) : "f"(lo), "f"(hi));
    return r;
}
__device__ __forceinline__ float2 unpack2(unsigned long long v) {
    float2 r;
    asm("mov.b64 {%0, %1}, %2;" : "=f"(r.x), "=f"(r.y) : "l"(v));
    return r;
}
__device__ __forceinline__ unsigned long long dup2(float v) { return pack2(v, v); }

__device__ __forceinline__ float warp_sum(float v) {
    v += __shfl_xor_sync(0xffffffffu, v, 16);
    v += __shfl_xor_sync(0xffffffffu, v, 8);
    v += __shfl_xor_sync(0xffffffffu, v, 4);
    v += __shfl_xor_sync(0xffffffffu, v, 2);
    v += __shfl_xor_sync(0xffffffffu, v, 1);
    return v;
}

// ============================================================================
// Kernel A: logits = W @ X + b, softmax over K, store weights S.
// Grid (32, 16) = (N/128, B), 128 threads.
// Tile: 64 k x 128 n. Microtile per thread: 8k x 8n (4 f32x2 pairs along n).
// W tile stored dup-packed (both halves = w) so no per-FMA packing needed.
// ============================================================================
__global__ __launch_bounds__(128) void k_softmax(
    const float* __restrict__ x, const float* __restrict__ Wc,
    const float* __restrict__ bc) {
    __shared__ unsigned long long Wsd[32 * 66];  // [dd][k] dup-packed, pad 66
    __shared__ float Xs[32 * 128];               // [dd][nn]
    __shared__ float red[8 * 128];

    const int t = threadIdx.x;
    const int b = blockIdx.y;
    const int n0 = blockIdx.x * 128;
    const int kg = t >> 4;       // 0..7 -> k = kg*8 + kk
    const int ng = t & 15;       // 0..15 -> n = ng*8 + c
    const float* xb = x + (size_t)b * D_ * N_;

    unsigned long long acc[8][4];
#pragma unroll
    for (int i = 0; i < 8; i++)
#pragma unroll
        for (int j = 0; j < 4; j++) acc[i][j] = 0ull;  // (0.0f, 0.0f)

    const int lk = t & 63;   // W-loader: k
    const int lh = t >> 6;   // W-loader: d-half

    for (int c = 0; c < 16; c++) {
        const int d0 = c * 32;
        // load W chunk (64 x 32), transposed + dup-packed
#pragma unroll
        for (int j = 0; j < 4; j++) {
            const float4 wv =
                *(const float4*)(Wc + lk * D_ + d0 + lh * 16 + j * 4);
            const int ddb = lh * 16 + j * 4;
            Wsd[(ddb + 0) * 66 + lk] = dup2(wv.x);
            Wsd[(ddb + 1) * 66 + lk] = dup2(wv.y);
            Wsd[(ddb + 2) * 66 + lk] = dup2(wv.z);
            Wsd[(ddb + 3) * 66 + lk] = dup2(wv.w);
        }
        // load X chunk (32 x 128), natural layout, fully coalesced
#pragma unroll
        for (int i = 0; i < 8; i++) {
            const int idx = i * 512 + t * 4;
            const int dd = idx >> 7, nn = idx & 127;
            *(float4*)(Xs + dd * 128 + nn) =
                *(const float4*)(xb + (size_t)(d0 + dd) * N_ + n0 + nn);
        }
        __syncthreads();
#pragma unroll 4
        for (int dd = 0; dd < 32; dd++) {
            const ulonglong2* wp =
                (const ulonglong2*)(Wsd + dd * 66 + kg * 8);
            const ulonglong2 w01 = wp[0], w23 = wp[1], w45 = wp[2], w67 = wp[3];
            const unsigned long long w2[8] = {w01.x, w01.y, w23.x, w23.y,
                                              w45.x, w45.y, w67.x, w67.y};
            const ulonglong2* xp = (const ulonglong2*)(Xs + dd * 128 + ng * 8);
            const ulonglong2 xa = xp[0], xb2 = xp[1];
            const unsigned long long xv[4] = {xa.x, xa.y, xb2.x, xb2.y};
#pragma unroll
            for (int kk = 0; kk < 8; kk++)
#pragma unroll
                for (int np = 0; np < 4; np++)
                    acc[kk][np] = fma2(w2[kk], xv[np], acc[kk][np]);
        }
        __syncthreads();
    }

    // bias
#pragma unroll
    for (int kk = 0; kk < 8; kk++) {
        const unsigned long long bd = dup2(__ldg(bc + kg * 8 + kk));
#pragma unroll
        for (int np = 0; np < 4; np++) acc[kk][np] = add2(acc[kk][np], bd);
    }

    // ---- softmax over K (8 kg groups x 8 local k) per column ----
    float lmax[8];
#pragma unroll
    for (int c2 = 0; c2 < 8; c2++) lmax[c2] = -3.0e38f;
#pragma unroll
    for (int kk = 0; kk < 8; kk++)
#pragma unroll
        for (int np = 0; np < 4; np++) {
            const float2 v = unpack2(acc[kk][np]);
            lmax[2 * np] = fmaxf(lmax[2 * np], v.x);
            lmax[2 * np + 1] = fmaxf(lmax[2 * np + 1], v.y);
        }
#pragma unroll
    for (int c2 = 0; c2 < 8; c2++) red[kg * 128 + ng * 8 + c2] = lmax[c2];
    __syncthreads();
    float cmax[8];
#pragma unroll
    for (int c2 = 0; c2 < 8; c2++) {
        float m = red[ng * 8 + c2];
#pragma unroll
        for (int j = 1; j < 8; j++) m = fmaxf(m, red[j * 128 + ng * 8 + c2]);
        cmax[c2] = m;
    }
    __syncthreads();

    float lsum[8];
#pragma unroll
    for (int c2 = 0; c2 < 8; c2++) lsum[c2] = 0.0f;
#pragma unroll
    for (int kk = 0; kk < 8; kk++)
#pragma unroll
        for (int np = 0; np < 4; np++) {
            const float2 v = unpack2(acc[kk][np]);
            const float e0 = __expf(v.x - cmax[2 * np]);
            const float e1 = __expf(v.y - cmax[2 * np + 1]);
            lsum[2 * np] += e0;
            lsum[2 * np + 1] += e1;
            acc[kk][np] = pack2(e0, e1);
        }
#pragma unroll
    for (int c2 = 0; c2 < 8; c2++) red[kg * 128 + ng * 8 + c2] = lsum[c2];
    __syncthreads();
    float inv[8];
#pragma unroll
    for (int c2 = 0; c2 < 8; c2++) {
        float s = red[ng * 8 + c2];
#pragma unroll
        for (int j = 1; j < 8; j++) s += red[j * 128 + ng * 8 + c2];
        inv[c2] = 1.0f / s;
    }

    // store S (coalesced per k-row)
#pragma unroll
    for (int kk = 0; kk < 8; kk++) {
        const float2 p0 = unpack2(acc[kk][0]);
        const float2 p1 = unpack2(acc[kk][1]);
        const float2 p2 = unpack2(acc[kk][2]);
        const float2 p3 = unpack2(acc[kk][3]);
        float4 o0, o1;
        o0.x = p0.x * inv[0]; o0.y = p0.y * inv[1];
        o0.z = p1.x * inv[2]; o0.w = p1.y * inv[3];
        o1.x = p2.x * inv[4]; o1.y = p2.y * inv[5];
        o1.z = p3.x * inv[6]; o1.w = p3.y * inv[7];
        float* sp = g_S + ((size_t)b * K_ + kg * 8 + kk) * N_ + n0 + ng * 8;
        *(float4*)(sp) = o0;
        *(float4*)(sp + 4) = o1;
    }
}

// ============================================================================
// Kernel W: wsum[b,k] = sum_n S[b,k,n]. Grid 1024 blocks (b*64+k), 128 threads.
// ============================================================================
__global__ __launch_bounds__(128) void k_wsum() {
    const int bk = blockIdx.x;
    const float* row = g_S + (size_t)bk * N_;
    const int t = threadIdx.x;
    float s = 0.0f;
#pragma unroll
    for (int i = 0; i < 8; i++) {
        const float4 v = *(const float4*)(row + t * 4 + i * 512);
        s += (v.x + v.y) + (v.z + v.w);
    }
    s = warp_sum(s);
    __shared__ float sm[4];
    if ((t & 31) == 0) sm[t >> 5] = s;
    __syncthreads();
    if (t == 0) g_wsum[bk] = (sm[0] + sm[1]) + (sm[2] + sm[3]);
}

// ============================================================================
// Kernel B: V[b,k,d] = sum_n S[b,k,n] * x[b,d,n]. Grid (4,16,2): d-tile 128,
// n-split 2 (each half written to its own partial buffer - no atomics).
// 256 threads, microtile 8k x 4d (2 f32x2 pairs along d). S dup-packed,
// X transposed into smem with coalesced warp-row loads.
// ============================================================================
__global__ __launch_bounds__(256) void k_wx(const float* __restrict__ x) {
    __shared__ unsigned long long Ssd[32 * 66];  // [nn][k] dup-packed
    __shared__ float Xt[32 * 132];               // [nn][dd] transposed, pad 132

    const int t = threadIdx.x;
    const int w = t >> 5, l = t & 31;
    const int d0 = blockIdx.x * 128;
    const int b = blockIdx.y;
    const int ns = blockIdx.z;
    const float* xb = x + (size_t)b * D_ * N_;
    const float* Sb = g_S + (size_t)b * K_ * N_;
    const int kg = t >> 5;   // 0..7
    const int dg = t & 31;   // 0..31
    const int loff = l >> 3; // loader row offset 0..3
    const int f4 = (l & 7) * 4;

    unsigned long long acc[8][2];
#pragma unroll
    for (int i = 0; i < 8; i++) { acc[i][0] = 0ull; acc[i][1] = 0ull; }

    for (int it = 0; it < 64; it++) {
        const int nb = ns * 2048 + it * 32;
        // load S chunk (64 k x 32 n), transposed + dup-packed, coalesced LDG
#pragma unroll
        for (int j = 0; j < 2; j++) {
            const int k = w * 8 + j * 4 + loff;
            const float4 sv = *(const float4*)(Sb + (size_t)k * N_ + nb + f4);
            Ssd[(f4 + 0) * 66 + k] = dup2(sv.x);
            Ssd[(f4 + 1) * 66 + k] = dup2(sv.y);
            Ssd[(f4 + 2) * 66 + k] = dup2(sv.z);
            Ssd[(f4 + 3) * 66 + k] = dup2(sv.w);
        }
        // load X chunk (128 d x 32 n), transposed, coalesced LDG
#pragma unroll
        for (int j = 0; j < 4; j++) {
            const int dd = w * 16 + j * 4 + loff;
            const float4 xv =
                *(const float4*)(xb + (size_t)(d0 + dd) * N_ + nb + f4);
            Xt[(f4 + 0) * 132 + dd] = xv.x;
            Xt[(f4 + 1) * 132 + dd] = xv.y;
            Xt[(f4 + 2) * 132 + dd] = xv.z;
            Xt[(f4 + 3) * 132 + dd] = xv.w;
        }
        __syncthreads();
#pragma unroll 4
        for (int nn = 0; nn < 32; nn++) {
            const ulonglong2* sp = (const ulonglong2*)(Ssd + nn * 66 + kg * 8);
            const ulonglong2 s01 = sp[0], s23 = sp[1], s45 = sp[2], s67 = sp[3];
            const unsigned long long s2[8] = {s01.x, s01.y, s23.x, s23.y,
                                              s45.x, s45.y, s67.x, s67.y};
            const ulonglong2 xp = *(const ulonglong2*)(Xt + nn * 132 + dg * 4);
#pragma unroll
            for (int kk = 0; kk < 8; kk++) {
                acc[kk][0] = fma2(s2[kk], xp.x, acc[kk][0]);
                acc[kk][1] = fma2(s2[kk], xp.y, acc[kk][1]);
            }
        }
        __syncthreads();
    }

    float* Vp = ns ? g_Vp1 : g_Vp0;
#pragma unroll
    for (int kk = 0; kk < 8; kk++) {
        const float2 p0 = unpack2(acc[kk][0]);
        const float2 p1 = unpack2(acc[kk][1]);
        float4 o; o.x = p0.x; o.y = p0.y; o.z = p1.x; o.w = p1.y;
        *(float4*)(Vp + ((size_t)b * K_ + kg * 8 + kk) * D_ + d0 + dg * 4) = o;
    }
}

// ============================================================================
// Kernel C1: vlad row = V - wsum*c, intra-L2-normalize, write out, emit norm^2.
// Grid (64,16), 128 threads (4 floats each).
// ============================================================================
__global__ __launch_bounds__(128) void k_norm1(
    const float* __restrict__ centers, float* __restrict__ out) {
    const int k = blockIdx.x, b = blockIdx.y, t = threadIdx.x;
    const size_t row = ((size_t)b * K_ + k) * D_;
    const float ws = g_wsum[b * K_ + k];
    const float4 v0 = *(const float4*)(g_Vp0 + row + t * 4);
    const float4 v1 = *(const float4*)(g_Vp1 + row + t * 4);
    const float4 c = *(const float4*)(centers + k * D_ + t * 4);
    float4 val;
    val.x = (v0.x + v1.x) - ws * c.x;
    val.y = (v0.y + v1.y) - ws * c.y;
    val.z = (v0.z + v1.z) - ws * c.z;
    val.w = (v0.w + v1.w) - ws * c.w;
    float ss = val.x * val.x + val.y * val.y + val.z * val.z + val.w * val.w;
    ss = warp_sum(ss);
    __shared__ float sm[4];
    if ((t & 31) == 0) sm[t >> 5] = ss;
    __syncthreads();
    const float total = (sm[0] + sm[1]) + (sm[2] + sm[3]);
    const float inv = 1.0f / fmaxf(sqrtf(total), EPSV);
    val.x *= inv; val.y *= inv; val.z *= inv; val.w *= inv;
    *(float4*)(out + row + t * 4) = val;
    if (t == 0) g_rn[b * K_ + k] = total * inv * inv;
}

// Kernel C1b: g_sumsq[b] = sum_k rownorm^2. Grid 16 blocks, 64 threads.
__global__ void k_rnsum() {
    const int b = blockIdx.x, t = threadIdx.x;
    float v = g_rn[b * K_ + t];
    v = warp_sum(v);
    __shared__ float sm[2];
    if ((t & 31) == 0) sm[t >> 5] = v;
    __syncthreads();
    if (t == 0) g_sumsq[b] = sm[0] + sm[1];
}

// Kernel C2: global L2 scale. Grid 512 x 256, one float4 per thread.
__global__ __launch_bounds__(256) void k_scale(float* __restrict__ out) {
    const int i4 = blockIdx.x * 256 + threadIdx.x;  // float4 index
    const int b = i4 >> 13;                          // 8192 float4 per batch
    const float inv = 1.0f / fmaxf(sqrtf(g_sumsq[b]), EPSV);
    float4 v = *(float4*)(out + (size_t)i4 * 4);
    v.x *= inv; v.y *= inv; v.z *= inv; v.w *= inv;
    *(float4*)(out + (size_t)i4 * 4) = v;
}

// ============================================================================
extern "C" void kernel_launch(void* const* d_in, const int* in_sizes, int n_in,
                              void* d_out, int out_size) {
    const float* x = (const float*)d_in[0];
    const float* conv_w = (const float*)d_in[1];
    const float* conv_b = (const float*)d_in[2];
    const float* centers = (const float*)d_in[3];
    float* out = (float*)d_out;

    k_softmax<<<dim3(32, 16), 128>>>(x, conv_w, conv_b);
    k_wsum<<<1024, 128>>>();
    k_wx<<<dim3(4, 16, 2), 256>>>(x);
    k_norm1<<<dim3(64, 16), 128>>>(centers, out);
    k_rnsum<<<16, 64>>>();
    k_scale<<<512, 256>>>(out);
}

// round 2
// speedup vs baseline: 1.0055x; 1.0055x over previous
#include <cuda_runtime.h>

#define B_ 16
#define D_ 512
#define N_ 4096
#define K_ 64
#define EPSV 1e-12f

// ---- scratch (static device globals; no runtime allocation) ----
__device__ float g_S[B_ * K_ * N_];        // softmax weights (16 MB)
__device__ float g_Vp0[B_ * K_ * D_];      // GEMM2 partial, n-split 0
__device__ float g_Vp1[B_ * K_ * D_];      // GEMM2 partial, n-split 1
__device__ float g_wsum[B_ * K_];
__device__ float g_rn[B_ * K_];            // per-row norm^2 after intra-normalize
__device__ float g_sumsq[B_];

// ---- packed f32x2 helpers (FFMA2: full-rate fp32 on sm_103a) ----
__device__ __forceinline__ unsigned long long fma2(unsigned long long a,
                                                   unsigned long long b,
                                                   unsigned long long c) {
    unsigned long long r;
    asm("fma.rn.f32x2 %0, %1, %2, %3;" : "=l"(r) : "l"(a), "l"(b), "l"(c));
    return r;
}
__device__ __forceinline__ unsigned long long add2(unsigned long long a,
                                                   unsigned long long b) {
    unsigned long long r;
    asm("add.rn.f32x2 %0, %1, %2;" : "=l"(r) : "l"(a), "l"(b));
    return r;
}
__device__ __forceinline__ unsigned long long pack2(float lo, float hi) {
    unsigned long long r;
    asm("mov.b64 %0, {%1, %2};" : "=l"(r) : "f"(lo), "f"(hi));
    return r;
}
__device__ __forceinline__ float2 unpack2(unsigned long long v) {
    float2 r;
    asm("mov.b64 {%0, %1}, %2;" : "=f"(r.x), "=f"(r.y) : "l"(v));
    return r;
}
__device__ __forceinline__ unsigned long long dup2(float v) { return pack2(v, v); }

__device__ __forceinline__ float warp_sum(float v) {
    v += __shfl_xor_sync(0xffffffffu, v, 16);
    v += __shfl_xor_sync(0xffffffffu, v, 8);
    v += __shfl_xor_sync(0xffffffffu, v, 4);
    v += __shfl_xor_sync(0xffffffffu, v, 2);
    v += __shfl_xor_sync(0xffffffffu, v, 1);
    return v;
}

// ============================================================================
// Kernel A: logits = W @ X + b, softmax over K, store weights S.
// Grid (32, 16) = (N/128, B), 128 threads.
// Tile: 64 k x 128 n. Microtile per thread: 8k x 8n (4 f32x2 pairs along n).
// W tile stored dup-packed (both halves = w) so no per-FMA packing needed.
// ============================================================================
__global__ __launch_bounds__(128) void k_softmax(
    const float* __restrict__ x, const float* __restrict__ Wc,
    const float* __restrict__ bc) {
    __shared__ unsigned long long Wsd[32 * 66];  // [dd][k] dup-packed, pad 66
    __shared__ float Xs[32 * 128];               // [dd][nn]
    __shared__ float red[8 * 128];

    const int t = threadIdx.x;
    const int b = blockIdx.y;
    const int n0 = blockIdx.x * 128;
    const int kg = t >> 4;       // 0..7 -> k = kg*8 + kk
    const int ng = t & 15;       // 0..15 -> n = ng*8 + c
    const float* xb = x + (size_t)b * D_ * N_;

    unsigned long long acc[8][4];
#pragma unroll
    for (int i = 0; i < 8; i++)
#pragma unroll
        for (int j = 0; j < 4; j++) acc[i][j] = 0ull;  // (0.0f, 0.0f)

    const int lk = t & 63;   // W-loader: k
    const int lh = t >> 6;   // W-loader: d-half

    for (int c = 0; c < 16; c++) {
        const int d0 = c * 32;
        // load W chunk (64 x 32), transposed + dup-packed
#pragma unroll
        for (int j = 0; j < 4; j++) {
            const float4 wv =
                *(const float4*)(Wc + lk * D_ + d0 + lh * 16 + j * 4);
            const int ddb = lh * 16 + j * 4;
            Wsd[(ddb + 0) * 66 + lk] = dup2(wv.x);
            Wsd[(ddb + 1) * 66 + lk] = dup2(wv.y);
            Wsd[(ddb + 2) * 66 + lk] = dup2(wv.z);
            Wsd[(ddb + 3) * 66 + lk] = dup2(wv.w);
        }
        // load X chunk (32 x 128), natural layout, fully coalesced
#pragma unroll
        for (int i = 0; i < 8; i++) {
            const int idx = i * 512 + t * 4;
            const int dd = idx >> 7, nn = idx & 127;
            *(float4*)(Xs + dd * 128 + nn) =
                *(const float4*)(xb + (size_t)(d0 + dd) * N_ + n0 + nn);
        }
        __syncthreads();
#pragma unroll 4
        for (int dd = 0; dd < 32; dd++) {
            const ulonglong2* wp =
                (const ulonglong2*)(Wsd + dd * 66 + kg * 8);
            const ulonglong2 w01 = wp[0], w23 = wp[1], w45 = wp[2], w67 = wp[3];
            const unsigned long long w2[8] = {w01.x, w01.y, w23.x, w23.y,
                                              w45.x, w45.y, w67.x, w67.y};
            const ulonglong2* xp = (const ulonglong2*)(Xs + dd * 128 + ng * 8);
            const ulonglong2 xa = xp[0], xb2 = xp[1];
            const unsigned long long xv[4] = {xa.x, xa.y, xb2.x, xb2.y};
#pragma unroll
            for (int kk = 0; kk < 8; kk++)
#pragma unroll
                for (int np = 0; np < 4; np++)
                    acc[kk][np] = fma2(w2[kk], xv[np], acc[kk][np]);
        }
        __syncthreads();
    }

    // bias
#pragma unroll
    for (int kk = 0; kk < 8; kk++) {
        const unsigned long long bd = dup2(__ldg(bc + kg * 8 + kk));
#pragma unroll
        for (int np = 0; np < 4; np++) acc[kk][np] = add2(acc[kk][np], bd);
    }

    // ---- softmax over K (8 kg groups x 8 local k) per column ----
    float lmax[8];
#pragma unroll
    for (int c2 = 0; c2 < 8; c2++) lmax[c2] = -3.0e38f;
#pragma unroll
    for (int kk = 0; kk < 8; kk++)
#pragma unroll
        for (int np = 0; np < 4; np++) {
            const float2 v = unpack2(acc[kk][np]);
            lmax[2 * np] = fmaxf(lmax[2 * np], v.x);
            lmax[2 * np + 1] = fmaxf(lmax[2 * np + 1], v.y);
        }
#pragma unroll
    for (int c2 = 0; c2 < 8; c2++) red[kg * 128 + ng * 8 + c2] = lmax[c2];
    __syncthreads();
    float cmax[8];
#pragma unroll
    for (int c2 = 0; c2 < 8; c2++) {
        float m = red[ng * 8 + c2];
#pragma unroll
        for (int j = 1; j < 8; j++) m = fmaxf(m, red[j * 128 + ng * 8 + c2]);
        cmax[c2] = m;
    }
    __syncthreads();

    float lsum[8];
#pragma unroll
    for (int c2 = 0; c2 < 8; c2++) lsum[c2] = 0.0f;
#pragma unroll
    for (int kk = 0; kk < 8; kk++)
#pragma unroll
        for (int np = 0; np < 4; np++) {
            const float2 v = unpack2(acc[kk][np]);
            const float e0 = __expf(v.x - cmax[2 * np]);
            const float e1 = __expf(v.y - cmax[2 * np + 1]);
            lsum[2 * np] += e0;
            lsum[2 * np + 1] += e1;
            acc[kk][np] = pack2(e0, e1);
        }
#pragma unroll
    for (int c2 = 0; c2 < 8; c2++) red[kg * 128 + ng * 8 + c2] = lsum[c2];
    __syncthreads();
    float inv[8];
#pragma unroll
    for (int c2 = 0; c2 < 8; c2++) {
        float s = red[ng * 8 + c2];
#pragma unroll
        for (int j = 1; j < 8; j++) s += red[j * 128 + ng * 8 + c2];
        inv[c2] = 1.0f / s;
    }

    // store S (coalesced per k-row)
#pragma unroll
    for (int kk = 0; kk < 8; kk++) {
        const float2 p0 = unpack2(acc[kk][0]);
        const float2 p1 = unpack2(acc[kk][1]);
        const float2 p2 = unpack2(acc[kk][2]);
        const float2 p3 = unpack2(acc[kk][3]);
        float4 o0, o1;
        o0.x = p0.x * inv[0]; o0.y = p0.y * inv[1];
        o0.z = p1.x * inv[2]; o0.w = p1.y * inv[3];
        o1.x = p2.x * inv[4]; o1.y = p2.y * inv[5];
        o1.z = p3.x * inv[6]; o1.w = p3.y * inv[7];
        float* sp = g_S + ((size_t)b * K_ + kg * 8 + kk) * N_ + n0 + ng * 8;
        *(float4*)(sp) = o0;
        *(float4*)(sp + 4) = o1;
    }
}

// ============================================================================
// Kernel W: wsum[b,k] = sum_n S[b,k,n]. Grid 1024 blocks (b*64+k), 128 threads.
// ============================================================================
__global__ __launch_bounds__(128) void k_wsum() {
    const int bk = blockIdx.x;
    const float* row = g_S + (size_t)bk * N_;
    const int t = threadIdx.x;
    float s = 0.0f;
#pragma unroll
    for (int i = 0; i < 8; i++) {
        const float4 v = *(const float4*)(row + t * 4 + i * 512);
        s += (v.x + v.y) + (v.z + v.w);
    }
    s = warp_sum(s);
    __shared__ float sm[4];
    if ((t & 31) == 0) sm[t >> 5] = s;
    __syncthreads();
    if (t == 0) g_wsum[bk] = (sm[0] + sm[1]) + (sm[2] + sm[3]);
}

// ============================================================================
// Kernel B: V[b,k,d] = sum_n S[b,k,n] * x[b,d,n]. Grid (4,16,2): d-tile 128,
// n-split 2 (each half written to its own partial buffer - no atomics).
// 256 threads, microtile 8k x 4d (2 f32x2 pairs along d). S dup-packed,
// X transposed into smem with coalesced warp-row loads.
// ============================================================================
__global__ __launch_bounds__(256) void k_wx(const float* __restrict__ x) {
    __shared__ unsigned long long Ssd[32 * 66];  // [nn][k] dup-packed
    __shared__ float Xt[32 * 132];               // [nn][dd] transposed, pad 132

    const int t = threadIdx.x;
    const int w = t >> 5, l = t & 31;
    const int d0 = blockIdx.x * 128;
    const int b = blockIdx.y;
    const int ns = blockIdx.z;
    const float* xb = x + (size_t)b * D_ * N_;
    const float* Sb = g_S + (size_t)b * K_ * N_;
    const int kg = t >> 5;   // 0..7
    const int dg = t & 31;   // 0..31
    const int loff = l >> 3; // loader row offset 0..3
    const int f4 = (l & 7) * 4;

    unsigned long long acc[8][2];
#pragma unroll
    for (int i = 0; i < 8; i++) { acc[i][0] = 0ull; acc[i][1] = 0ull; }

    for (int it = 0; it < 64; it++) {
        const int nb = ns * 2048 + it * 32;
        // load S chunk (64 k x 32 n), transposed + dup-packed, coalesced LDG
#pragma unroll
        for (int j = 0; j < 2; j++) {
            const int k = w * 8 + j * 4 + loff;
            const float4 sv = *(const float4*)(Sb + (size_t)k * N_ + nb + f4);
            Ssd[(f4 + 0) * 66 + k] = dup2(sv.x);
            Ssd[(f4 + 1) * 66 + k] = dup2(sv.y);
            Ssd[(f4 + 2) * 66 + k] = dup2(sv.z);
            Ssd[(f4 + 3) * 66 + k] = dup2(sv.w);
        }
        // load X chunk (128 d x 32 n), transposed, coalesced LDG
#pragma unroll
        for (int j = 0; j < 4; j++) {
            const int dd = w * 16 + j * 4 + loff;
            const float4 xv =
                *(const float4*)(xb + (size_t)(d0 + dd) * N_ + nb + f4);
            Xt[(f4 + 0) * 132 + dd] = xv.x;
            Xt[(f4 + 1) * 132 + dd] = xv.y;
            Xt[(f4 + 2) * 132 + dd] = xv.z;
            Xt[(f4 + 3) * 132 + dd] = xv.w;
        }
        __syncthreads();
#pragma unroll 4
        for (int nn = 0; nn < 32; nn++) {
            const ulonglong2* sp = (const ulonglong2*)(Ssd + nn * 66 + kg * 8);
            const ulonglong2 s01 = sp[0], s23 = sp[1], s45 = sp[2], s67 = sp[3];
            const unsigned long long s2[8] = {s01.x, s01.y, s23.x, s23.y,
                                              s45.x, s45.y, s67.x, s67.y};
            const ulonglong2 xp = *(const ulonglong2*)(Xt + nn * 132 + dg * 4);
#pragma unroll
            for (int kk = 0; kk < 8; kk++) {
                acc[kk][0] = fma2(s2[kk], xp.x, acc[kk][0]);
                acc[kk][1] = fma2(s2[kk], xp.y, acc[kk][1]);
            }
        }
        __syncthreads();
    }

    float* Vp = ns ? g_Vp1 : g_Vp0;
#pragma unroll
    for (int kk = 0; kk < 8; kk++) {
        const float2 p0 = unpack2(acc[kk][0]);
        const float2 p1 = unpack2(acc[kk][1]);
        float4 o; o.x = p0.x; o.y = p0.y; o.z = p1.x; o.w = p1.y;
        *(float4*)(Vp + ((size_t)b * K_ + kg * 8 + kk) * D_ + d0 + dg * 4) = o;
    }
}

// ============================================================================
// Kernel C1: vlad row = V - wsum*c, intra-L2-normalize, write out, emit norm^2.
// Grid (64,16), 128 threads (4 floats each).
// ============================================================================
__global__ __launch_bounds__(128) void k_norm1(
    const float* __restrict__ centers, float* __restrict__ out) {
    const int k = blockIdx.x, b = blockIdx.y, t = threadIdx.x;
    const size_t row = ((size_t)b * K_ + k) * D_;
    const float ws = g_wsum[b * K_ + k];
    const float4 v0 = *(const float4*)(g_Vp0 + row + t * 4);
    const float4 v1 = *(const float4*)(g_Vp1 + row + t * 4);
    const float4 c = *(const float4*)(centers + k * D_ + t * 4);
    float4 val;
    val.x = (v0.x + v1.x) - ws * c.x;
    val.y = (v0.y + v1.y) - ws * c.y;
    val.z = (v0.z + v1.z) - ws * c.z;
    val.w = (v0.w + v1.w) - ws * c.w;
    float ss = val.x * val.x + val.y * val.y + val.z * val.z + val.w * val.w;
    ss = warp_sum(ss);
    __shared__ float sm[4];
    if ((t & 31) == 0) sm[t >> 5] = ss;
    __syncthreads();
    const float total = (sm[0] + sm[1]) + (sm[2] + sm[3]);
    const float inv = 1.0f / fmaxf(sqrtf(total), EPSV);
    val.x *= inv; val.y *= inv; val.z *= inv; val.w *= inv;
    *(float4*)(out + row + t * 4) = val;
    if (t == 0) g_rn[b * K_ + k] = total * inv * inv;
}

// Kernel C1b: g_sumsq[b] = sum_k rownorm^2. Grid 16 blocks, 64 threads.
__global__ void k_rnsum() {
    const int b = blockIdx.x, t = threadIdx.x;
    float v = g_rn[b * K_ + t];
    v = warp_sum(v);
    __shared__ float sm[2];
    if ((t & 31) == 0) sm[t >> 5] = v;
    __syncthreads();
    if (t == 0) g_sumsq[b] = sm[0] + sm[1];
}

// Kernel C2: global L2 scale. Grid 512 x 256, one float4 per thread.
__global__ __launch_bounds__(256) void k_scale(float* __restrict__ out) {
    const int i4 = blockIdx.x * 256 + threadIdx.x;  // float4 index
    const int b = i4 >> 13;                          // 8192 float4 per batch
    const float inv = 1.0f / fmaxf(sqrtf(g_sumsq[b]), EPSV);
    float4 v = *(float4*)(out + (size_t)i4 * 4);
    v.x *= inv; v.y *= inv; v.z *= inv; v.w *= inv;
    *(float4*)(out + (size_t)i4 * 4) = v;
}

// ============================================================================
extern "C" void kernel_launch(void* const* d_in, const int* in_sizes, int n_in,
                              void* d_out, int out_size) {
    const float* x = (const float*)d_in[0];
    const float* conv_w = (const float*)d_in[1];
    const float* conv_b = (const float*)d_in[2];
    const float* centers = (const float*)d_in[3];
    float* out = (float*)d_out;

    k_softmax<<<dim3(32, 16), 128>>>(x, conv_w, conv_b);
    k_wsum<<<1024, 128>>>();
    k_wx<<<dim3(4, 16, 2), 256>>>(x);
    k_norm1<<<dim3(64, 16), 128>>>(centers, out);
    k_rnsum<<<16, 64>>>();
    k_scale<<<512, 256>>>(out);
}

// round 4
// speedup vs baseline: 3.1202x; 3.1031x over previous
#include <cuda_runtime.h>
#include <cuda_bf16.h>
#include <cstdint>

#define B_ 16
#define D_ 512
#define N_ 4096
#define K_ 64
#define EPSV 1e-12f

// ---- scratch ----
__device__ uint32_t g_Spk[B_ * K_ * N_];   // packed (hi | lo<<16) bf16 softmax weights
__device__ float g_Vp[4 * B_ * K_ * D_];   // GEMM2 partials (n-split 4)
__device__ float g_wsum[B_ * K_];
__device__ float g_rn[B_ * K_];
__device__ float g_sumsq[B_];

// ============================ helpers ============================
__device__ __forceinline__ uint32_t smem_to_u32(const void* p) {
    uint32_t a;
    asm("{ .reg .u64 t; cvta.to.shared.u64 t, %1; cvt.u32.u64 %0, t; }" : "=r"(a) : "l"(p));
    return a;
}
__device__ __forceinline__ void ldsm4(uint32_t a, uint32_t r[4]) {
    asm volatile("ldmatrix.sync.aligned.m8n8.x4.shared.b16 {%0,%1,%2,%3},[%4];"
                 : "=r"(r[0]), "=r"(r[1]), "=r"(r[2]), "=r"(r[3]) : "r"(a));
}
__device__ __forceinline__ void ldsm4t(uint32_t a, uint32_t r[4]) {
    asm volatile("ldmatrix.sync.aligned.m8n8.x4.trans.shared.b16 {%0,%1,%2,%3},[%4];"
                 : "=r"(r[0]), "=r"(r[1]), "=r"(r[2]), "=r"(r[3]) : "r"(a));
}
__device__ __forceinline__ void mma_bf16(float c[4], const uint32_t a[4],
                                         uint32_t b0, uint32_t b1) {
    asm volatile(
        "mma.sync.aligned.m16n8k16.row.col.f32.bf16.bf16.f32 "
        "{%0,%1,%2,%3},{%4,%5,%6,%7},{%8,%9},{%0,%1,%2,%3};"
        : "+f"(c[0]), "+f"(c[1]), "+f"(c[2]), "+f"(c[3])
        : "r"(a[0]), "r"(a[1]), "r"(a[2]), "r"(a[3]), "r"(b0), "r"(b1));
}
__device__ __forceinline__ void sts64(uint32_t a, uint32_t r0, uint32_t r1) {
    asm volatile("st.shared.v2.b32 [%0],{%1,%2};" :: "r"(a), "r"(r0), "r"(r1) : "memory");
}
// f0,f1 -> hi bf16x2 (f0 low), lo bf16x2 (residuals)
__device__ __forceinline__ void cvt_hilo(float f0, float f1, uint32_t& h, uint32_t& l) {
    asm("cvt.rn.bf16x2.f32 %0, %1, %2;" : "=r"(h) : "f"(f1), "f"(f0));
    const float fh0 = __uint_as_float(h << 16);
    const float fh1 = __uint_as_float(h & 0xffff0000u);
    asm("cvt.rn.bf16x2.f32 %0, %1, %2;" : "=r"(l) : "f"(f1 - fh1), "f"(f0 - fh0));
}
// f -> (hi16 | lo16<<16)
__device__ __forceinline__ uint32_t pack_hilo(float f) {
    uint32_t h, l;
    asm("cvt.rn.bf16x2.f32 %0, %1, %2;" : "=r"(h) : "f"(0.0f), "f"(f));
    const float fh = __uint_as_float(h << 16);
    asm("cvt.rn.bf16x2.f32 %0, %1, %2;" : "=r"(l) : "f"(0.0f), "f"(f - fh));
    return (h & 0xffffu) | (l << 16);
}
__device__ __forceinline__ float warp_sum(float v) {
    v += __shfl_xor_sync(0xffffffffu, v, 16);
    v += __shfl_xor_sync(0xffffffffu, v, 8);
    v += __shfl_xor_sync(0xffffffffu, v, 4);
    v += __shfl_xor_sync(0xffffffffu, v, 2);
    v += __shfl_xor_sync(0xffffffffu, v, 1);
    return v;
}

// ============================================================================
// G1: logits = x^T W^T + b (split-bf16, 4 terms) -> softmax over 64 -> packed S
// grid (32, 16), 256 thr. Block: 128 tokens x 64 clusters, K=512 (8 chunks).
// smem: X[d64][n128] hi/lo (16KB ea), W[cl64][d64] hi/lo (8KB ea), bias.
// ============================================================================
#define XHI 0
#define XLO 16384
#define WHI 32768
#define WLO 40960
#define BIASOF 49152
#define G1_SMEM 49408

__global__ __launch_bounds__(256, 2) void g1_softmax(
    const float* __restrict__ x, const float* __restrict__ Wc,
    const float* __restrict__ bc) {
    extern __shared__ char smem[];
    const uint32_t sb = smem_to_u32(smem);
    const int t = threadIdx.x, T = t & 31, w = t >> 5;
    const int b = blockIdx.y, n0 = blockIdx.x * 128;
    const float* xb = x + (size_t)b * (D_ * N_);
    if (t < 64) ((float*)(smem + BIASOF))[t] = bc[t];

    float acc[8][4];
#pragma unroll
    for (int j = 0; j < 8; j++)
#pragma unroll
        for (int i = 0; i < 4; i++) acc[j][i] = 0.0f;

    // ldmatrix lane components
    const int ak = ((T >> 4) & 1) * 8 + (T & 7);         // A: k(d) row offset
    const int am = (w * 16 + ((T >> 3) & 1) * 8) * 2;    // A: m(token) byte col
    const int bn = ((T >> 4) & 1) * 8 + (T & 7);         // B: n row offset
    const int bkb = ((T >> 3) & 1) * 16;                 // B: k byte col offset
    const int wcl = t >> 2;

    for (int c = 0; c < 8; c++) {
        const int d0 = c * 64;
        float4 xv[8];
#pragma unroll
        for (int i = 0; i < 8; i++)
            xv[i] = *(const float4*)(xb + (size_t)(d0 + i * 8 + w) * N_ + n0 + T * 4);
        float4 wv[4];
#pragma unroll
        for (int i = 0; i < 4; i++)
            wv[i] = *(const float4*)(Wc + (size_t)wcl * D_ + d0 + (t & 3) * 4 + i * 16);

        __syncthreads();   // prev chunk's ldmatrix complete
#pragma unroll
        for (int i = 0; i < 8; i++) {
            const int dd = i * 8 + w;
            const uint32_t col = (uint32_t)(T * 8) ^ (uint32_t)((dd & 7) << 4);
            uint32_t h0, l0, h1, l1;
            cvt_hilo(xv[i].x, xv[i].y, h0, l0);
            cvt_hilo(xv[i].z, xv[i].w, h1, l1);
            sts64(sb + XHI + dd * 256 + col, h0, h1);
            sts64(sb + XLO + dd * 256 + col, l0, l1);
        }
#pragma unroll
        for (int i = 0; i < 4; i++) {
            const uint32_t col =
                (uint32_t)((t & 3) * 8 + i * 32) ^ (uint32_t)((wcl & 7) << 4);
            uint32_t h0, l0, h1, l1;
            cvt_hilo(wv[i].x, wv[i].y, h0, l0);
            cvt_hilo(wv[i].z, wv[i].w, h1, l1);
            sts64(sb + WHI + wcl * 128 + col, h0, h1);
            sts64(sb + WLO + wcl * 128 + col, l0, l1);
        }
        __syncthreads();

#pragma unroll
        for (int ks = 0; ks < 4; ks++) {
            const int kd = ks * 16;
            const int arow = kd + ak;
            const uint32_t aaddr =
                sb + XHI + arow * 256 + ((uint32_t)am ^ (uint32_t)((arow & 7) << 4));
            uint32_t ah[4], al[4];
            ldsm4t(aaddr, ah);
            ldsm4t(aaddr + (XLO - XHI), al);
            uint32_t bh[4][4], bl[4][4];
#pragma unroll
            for (int g = 0; g < 4; g++) {
                const int brow = g * 16 + bn;
                const uint32_t baddr = sb + WHI + brow * 128 +
                    ((uint32_t)(kd * 2 + bkb) ^ (uint32_t)((brow & 7) << 4));
                ldsm4(baddr, bh[g]);
                ldsm4(baddr + (WLO - WHI), bl[g]);
            }
#pragma unroll
            for (int g = 0; g < 4; g++) {
                mma_bf16(acc[2 * g], ah, bh[g][0], bh[g][1]);
                mma_bf16(acc[2 * g + 1], ah, bh[g][2], bh[g][3]);
            }
#pragma unroll
            for (int g = 0; g < 4; g++) {
                mma_bf16(acc[2 * g], ah, bl[g][0], bl[g][1]);
                mma_bf16(acc[2 * g + 1], ah, bl[g][2], bl[g][3]);
            }
#pragma unroll
            for (int g = 0; g < 4; g++) {
                mma_bf16(acc[2 * g], al, bh[g][0], bh[g][1]);
                mma_bf16(acc[2 * g + 1], al, bh[g][2], bh[g][3]);
            }
#pragma unroll
            for (int g = 0; g < 4; g++) {
                mma_bf16(acc[2 * g], al, bl[g][0], bl[g][1]);
                mma_bf16(acc[2 * g + 1], al, bl[g][2], bl[g][3]);
            }
        }
    }
    __syncthreads();

    // bias + softmax (rows r0 = w*16 + T/4, r1 = r0+8; quad holds full 64 cl)
    const float* bias = (const float*)(smem + BIASOF);
    float m0 = -3.0e38f, m1 = -3.0e38f;
#pragma unroll
    for (int j = 0; j < 8; j++) {
        const float bb0 = bias[j * 8 + (T & 3) * 2];
        const float bb1 = bias[j * 8 + (T & 3) * 2 + 1];
        acc[j][0] += bb0; acc[j][1] += bb1;
        acc[j][2] += bb0; acc[j][3] += bb1;
        m0 = fmaxf(m0, fmaxf(acc[j][0], acc[j][1]));
        m1 = fmaxf(m1, fmaxf(acc[j][2], acc[j][3]));
    }
    m0 = fmaxf(m0, __shfl_xor_sync(0xffffffffu, m0, 1));
    m0 = fmaxf(m0, __shfl_xor_sync(0xffffffffu, m0, 2));
    m1 = fmaxf(m1, __shfl_xor_sync(0xffffffffu, m1, 1));
    m1 = fmaxf(m1, __shfl_xor_sync(0xffffffffu, m1, 2));
    float s0 = 0.0f, s1 = 0.0f;
#pragma unroll
    for (int j = 0; j < 8; j++) {
        acc[j][0] = __expf(acc[j][0] - m0); s0 += acc[j][0];
        acc[j][1] = __expf(acc[j][1] - m0); s0 += acc[j][1];
        acc[j][2] = __expf(acc[j][2] - m1); s1 += acc[j][2];
        acc[j][3] = __expf(acc[j][3] - m1); s1 += acc[j][3];
    }
    s0 += __shfl_xor_sync(0xffffffffu, s0, 1);
    s0 += __shfl_xor_sync(0xffffffffu, s0, 2);
    s1 += __shfl_xor_sync(0xffffffffu, s1, 1);
    s1 += __shfl_xor_sync(0xffffffffu, s1, 2);
    const float inv0 = 1.0f / s0, inv1 = 1.0f / s1;

    uint32_t* Ts = (uint32_t*)smem;   // [64][132] padded
    const int tok0 = w * 16 + (T >> 2), tok1 = tok0 + 8;
#pragma unroll
    for (int j = 0; j < 8; j++) {
        const int cl = j * 8 + (T & 3) * 2;
        Ts[cl * 132 + tok0] = pack_hilo(acc[j][0] * inv0);
        Ts[(cl + 1) * 132 + tok0] = pack_hilo(acc[j][1] * inv0);
        Ts[cl * 132 + tok1] = pack_hilo(acc[j][2] * inv1);
        Ts[(cl + 1) * 132 + tok1] = pack_hilo(acc[j][3] * inv1);
    }
    __syncthreads();
    const int cl = t >> 2;
    uint32_t* Sg = g_Spk + (size_t)(b * 64 + cl) * N_ + n0;
#pragma unroll
    for (int jj = 0; jj < 8; jj++) {
        const int colx = (t & 3) * 4 + jj * 16;
        uint4 v;
        v.x = Ts[cl * 132 + colx];     v.y = Ts[cl * 132 + colx + 1];
        v.z = Ts[cl * 132 + colx + 2]; v.w = Ts[cl * 132 + colx + 3];
        *(uint4*)(Sg + colx) = v;
    }
}

// ============================================================================
// G2: V[d,k] = sum_n x[d,n] * S[n,k] (split-bf16, 3 terms).
// grid (4 dtile, 16 b, 4 nsplit), 256 thr. Block: 128 d x 64 cl, K=1024 n.
// ============================================================================
#define AHI 0
#define ALO 16384
#define BHI 32768
#define BLO 40960
#define G2_SMEM 49152

__global__ __launch_bounds__(256, 2) void g2_wx(const float* __restrict__ x) {
    extern __shared__ char smem[];
    const uint32_t sb = smem_to_u32(smem);
    const int t = threadIdx.x, T = t & 31, w = t >> 5;
    const int d0 = blockIdx.x * 128, b = blockIdx.y, ns = blockIdx.z;
    const float* xb = x + (size_t)b * (D_ * N_);
    const uint32_t* Sb = g_Spk + (size_t)b * (K_ * N_);

    float acc[8][4];
#pragma unroll
    for (int j = 0; j < 8; j++)
#pragma unroll
        for (int i = 0; i < 4; i++) acc[j][i] = 0.0f;

    const int am8 = ((T >> 3) & 1) * 8;
    const int akb = ((T >> 4) & 1) * 16;
    const int bn = ((T >> 4) & 1) * 8 + (T & 7);
    const int bkb = ((T >> 3) & 1) * 16;
    const int scl = t >> 2;

    for (int ch = 0; ch < 16; ch++) {
        const int nb = ns * 1024 + ch * 64;
        float4 xv[8];
#pragma unroll
        for (int i = 0; i < 8; i++)
            xv[i] = *(const float4*)(xb + (size_t)(d0 + i * 16 + (t >> 4)) * N_ +
                                     nb + (t & 15) * 4);
        uint4 sv[4];
#pragma unroll
        for (int i = 0; i < 4; i++)
            sv[i] = *(const uint4*)(Sb + (size_t)scl * N_ + nb + (t & 3) * 4 + i * 16);

        __syncthreads();
#pragma unroll
        for (int i = 0; i < 8; i++) {
            const int dd = i * 16 + (t >> 4);
            const uint32_t col = (uint32_t)((t & 15) * 8) ^ (uint32_t)((dd & 7) << 4);
            uint32_t h0, l0, h1, l1;
            cvt_hilo(xv[i].x, xv[i].y, h0, l0);
            cvt_hilo(xv[i].z, xv[i].w, h1, l1);
            sts64(sb + AHI + dd * 128 + col, h0, h1);
            sts64(sb + ALO + dd * 128 + col, l0, l1);
        }
#pragma unroll
        for (int i = 0; i < 4; i++) {
            const uint32_t col =
                (uint32_t)((t & 3) * 8 + i * 32) ^ (uint32_t)((scl & 7) << 4);
            sts64(sb + BHI + scl * 128 + col,
                  __byte_perm(sv[i].x, sv[i].y, 0x5410),
                  __byte_perm(sv[i].z, sv[i].w, 0x5410));
            sts64(sb + BLO + scl * 128 + col,
                  __byte_perm(sv[i].x, sv[i].y, 0x7632),
                  __byte_perm(sv[i].z, sv[i].w, 0x7632));
        }
        __syncthreads();

#pragma unroll
        for (int ks = 0; ks < 4; ks++) {
            const int kd = ks * 16;
            const int arow = w * 16 + am8 + (T & 7);
            const uint32_t aaddr = sb + AHI + arow * 128 +
                ((uint32_t)(kd * 2 + akb) ^ (uint32_t)((arow & 7) << 4));
            uint32_t ah[4], al[4];
            ldsm4(aaddr, ah);
            ldsm4(aaddr + (ALO - AHI), al);
            uint32_t bh[4][4], bl[4][4];
#pragma unroll
            for (int g = 0; g < 4; g++) {
                const int brow = g * 16 + bn;
                const uint32_t baddr = sb + BHI + brow * 128 +
                    ((uint32_t)(kd * 2 + bkb) ^ (uint32_t)((brow & 7) << 4));
                ldsm4(baddr, bh[g]);
                ldsm4(baddr + (BLO - BHI), bl[g]);
            }
#pragma unroll
            for (int g = 0; g < 4; g++) {
                mma_bf16(acc[2 * g], ah, bh[g][0], bh[g][1]);
                mma_bf16(acc[2 * g + 1], ah, bh[g][2], bh[g][3]);
            }
#pragma unroll
            for (int g = 0; g < 4; g++) {
                mma_bf16(acc[2 * g], ah, bl[g][0], bl[g][1]);
                mma_bf16(acc[2 * g + 1], ah, bl[g][2], bl[g][3]);
            }
#pragma unroll
            for (int g = 0; g < 4; g++) {
                mma_bf16(acc[2 * g], al, bh[g][0], bh[g][1]);
                mma_bf16(acc[2 * g + 1], al, bh[g][2], bh[g][3]);
            }
        }
    }
    __syncthreads();

    // smem transpose -> coalesced [k][d] stores
    float* Vt = (float*)smem;   // [64][132] padded
    const int dd0 = w * 16 + (T >> 2), dd1 = dd0 + 8;
#pragma unroll
    for (int j = 0; j < 8; j++) {
        const int cl = j * 8 + (T & 3) * 2;
        Vt[cl * 132 + dd0] = acc[j][0];
        Vt[(cl + 1) * 132 + dd0] = acc[j][1];
        Vt[cl * 132 + dd1] = acc[j][2];
        Vt[(cl + 1) * 132 + dd1] = acc[j][3];
    }
    __syncthreads();
    float* Vp = g_Vp + (size_t)ns * (B_ * K_ * D_);
    const int cl = t >> 2;
    float* dst = Vp + (size_t)(b * 64 + cl) * D_ + d0;
#pragma unroll
    for (int jj = 0; jj < 8; jj++) {
        const int colx = (t & 3) * 4 + jj * 16;
        float4 v;
        v.x = Vt[cl * 132 + colx];     v.y = Vt[cl * 132 + colx + 1];
        v.z = Vt[cl * 132 + colx + 2]; v.w = Vt[cl * 132 + colx + 3];
        *(float4*)(dst + colx) = v;
    }
}

// ============================================================================
// wsum[b,k] = sum_n (hi+lo). Grid 1024, 128 threads.
// ============================================================================
__global__ __launch_bounds__(128) void k_wsum() {
    const int bk = blockIdx.x, t = threadIdx.x;
    const uint32_t* row = g_Spk + (size_t)bk * N_;
    float s = 0.0f;
#pragma unroll
    for (int q = 0; q < 8; q++) {
        const uint4 v = *(const uint4*)(row + q * 512 + t * 4);
        const uint32_t u[4] = {v.x, v.y, v.z, v.w};
#pragma unroll
        for (int i = 0; i < 4; i++) {
            s += __uint_as_float(u[i] << 16);            // hi bf16 -> f32
            s += __uint_as_float(u[i] & 0xffff0000u);    // lo bf16 -> f32
        }
    }
    s = warp_sum(s);
    __shared__ float sm[4];
    if ((t & 31) == 0) sm[t >> 5] = s;
    __syncthreads();
    if (t == 0) g_wsum[bk] = (sm[0] + sm[1]) + (sm[2] + sm[3]);
}

// ============================================================================
// norm1: vlad = sum(4 partials) - wsum*c, intra-L2-normalize, emit norm^2.
// ============================================================================
__global__ __launch_bounds__(128) void k_norm1(
    const float* __restrict__ centers, float* __restrict__ out) {
    const int k = blockIdx.x, b = blockIdx.y, t = threadIdx.x;
    const size_t row = ((size_t)b * K_ + k) * D_;
    const float ws = g_wsum[b * K_ + k];
    const float4 v0 = *(const float4*)(g_Vp + row + t * 4);
    const float4 v1 = *(const float4*)(g_Vp + (size_t)(B_ * K_ * D_) + row + t * 4);
    const float4 v2 = *(const float4*)(g_Vp + (size_t)2 * (B_ * K_ * D_) + row + t * 4);
    const float4 v3 = *(const float4*)(g_Vp + (size_t)3 * (B_ * K_ * D_) + row + t * 4);
    const float4 c = *(const float4*)(centers + k * D_ + t * 4);
    float4 val;
    val.x = ((v0.x + v1.x) + (v2.x + v3.x)) - ws * c.x;
    val.y = ((v0.y + v1.y) + (v2.y + v3.y)) - ws * c.y;
    val.z = ((v0.z + v1.z) + (v2.z + v3.z)) - ws * c.z;
    val.w = ((v0.w + v1.w) + (v2.w + v3.w)) - ws * c.w;
    float ss = val.x * val.x + val.y * val.y + val.z * val.z + val.w * val.w;
    ss = warp_sum(ss);
    __shared__ float sm[4];
    if ((t & 31) == 0) sm[t >> 5] = ss;
    __syncthreads();
    const float total = (sm[0] + sm[1]) + (sm[2] + sm[3]);
    const float inv = 1.0f / fmaxf(sqrtf(total), EPSV);
    val.x *= inv; val.y *= inv; val.z *= inv; val.w *= inv;
    *(float4*)(out + row + t * 4) = val;
    if (t == 0) g_rn[b * K_ + k] = total * inv * inv;
}

__global__ void k_rnsum() {
    const int b = blockIdx.x, t = threadIdx.x;
    float v = g_rn[b * K_ + t];
    v = warp_sum(v);
    __shared__ float sm[2];
    if ((t & 31) == 0) sm[t >> 5] = v;
    __syncthreads();
    if (t == 0) g_sumsq[b] = sm[0] + sm[1];
}

__global__ __launch_bounds__(256) void k_scale(float* __restrict__ out) {
    const int i4 = blockIdx.x * 256 + threadIdx.x;
    const int b = i4 >> 13;
    const float inv = 1.0f / fmaxf(sqrtf(g_sumsq[b]), EPSV);
    float4 v = *(float4*)(out + (size_t)i4 * 4);
    v.x *= inv; v.y *= inv; v.z *= inv; v.w *= inv;
    *(float4*)(out + (size_t)i4 * 4) = v;
}

// ============================================================================
extern "C" void kernel_launch(void* const* d_in, const int* in_sizes, int n_in,
                              void* d_out, int out_size) {
    const float* x = (const float*)d_in[0];
    const float* conv_w = (const float*)d_in[1];
    const float* conv_b = (const float*)d_in[2];
    const float* centers = (const float*)d_in[3];
    float* out = (float*)d_out;

    cudaFuncSetAttribute(g1_softmax, cudaFuncAttributeMaxDynamicSharedMemorySize, G1_SMEM);
    cudaFuncSetAttribute(g2_wx, cudaFuncAttributeMaxDynamicSharedMemorySize, G2_SMEM);

    g1_softmax<<<dim3(32, 16), 256, G1_SMEM>>>(x, conv_w, conv_b);
    k_wsum<<<1024, 128>>>();
    g2_wx<<<dim3(4, 16, 4), 256, G2_SMEM>>>(x);
    k_norm1<<<dim3(64, 16), 128>>>(centers, out);
    k_rnsum<<<16, 64>>>();
    k_scale<<<512, 256>>>(out);
}

// round 5
// speedup vs baseline: 3.4203x; 1.0961x over previous
#include <cuda_runtime.h>
#include <cuda_bf16.h>
#include <cstdint>

#define B_ 16
#define D_ 512
#define N_ 4096
#define K_ 64
#define EPSV 1e-12f

// ---- scratch ----
__device__ uint32_t g_Spk[B_ * K_ * N_];   // packed (hi | lo<<16) bf16 softmax weights
__device__ float g_Vp[4 * B_ * K_ * D_];   // GEMM2 partials (n-split 4)
__device__ float g_wsumP[B_ * 32 * K_];    // per-(b, ntile, k) wsum partials
__device__ float g_rn[B_ * K_];
__device__ float g_sumsq[B_];

// ============================ helpers ============================
__device__ __forceinline__ uint32_t smem_to_u32(const void* p) {
    uint32_t a;
    asm("{ .reg .u64 t; cvta.to.shared.u64 t, %1; cvt.u32.u64 %0, t; }" : "=r"(a) : "l"(p));
    return a;
}
__device__ __forceinline__ void ldsm4(uint32_t a, uint32_t r[4]) {
    asm volatile("ldmatrix.sync.aligned.m8n8.x4.shared.b16 {%0,%1,%2,%3},[%4];"
                 : "=r"(r[0]), "=r"(r[1]), "=r"(r[2]), "=r"(r[3]) : "r"(a));
}
__device__ __forceinline__ void ldsm4t(uint32_t a, uint32_t r[4]) {
    asm volatile("ldmatrix.sync.aligned.m8n8.x4.trans.shared.b16 {%0,%1,%2,%3},[%4];"
                 : "=r"(r[0]), "=r"(r[1]), "=r"(r[2]), "=r"(r[3]) : "r"(a));
}
__device__ __forceinline__ void mma_bf16(float c[4], const uint32_t a[4],
                                         uint32_t b0, uint32_t b1) {
    asm volatile(
        "mma.sync.aligned.m16n8k16.row.col.f32.bf16.bf16.f32 "
        "{%0,%1,%2,%3},{%4,%5,%6,%7},{%8,%9},{%0,%1,%2,%3};"
        : "+f"(c[0]), "+f"(c[1]), "+f"(c[2]), "+f"(c[3])
        : "r"(a[0]), "r"(a[1]), "r"(a[2]), "r"(a[3]), "r"(b0), "r"(b1));
}
__device__ __forceinline__ void sts64(uint32_t a, uint32_t r0, uint32_t r1) {
    asm volatile("st.shared.v2.b32 [%0],{%1,%2};" :: "r"(a), "r"(r0), "r"(r1) : "memory");
}
// f0,f1 -> hi bf16x2 (f0 low), lo bf16x2 (residuals)
__device__ __forceinline__ void cvt_hilo(float f0, float f1, uint32_t& h, uint32_t& l) {
    asm("cvt.rn.bf16x2.f32 %0, %1, %2;" : "=r"(h) : "f"(f1), "f"(f0));
    const float fh0 = __uint_as_float(h << 16);
    const float fh1 = __uint_as_float(h & 0xffff0000u);
    asm("cvt.rn.bf16x2.f32 %0, %1, %2;" : "=r"(l) : "f"(f1 - fh1), "f"(f0 - fh0));
}
// f -> (hi16 | lo16<<16)
__device__ __forceinline__ uint32_t pack_hilo(float f) {
    uint32_t h, l;
    asm("cvt.rn.bf16x2.f32 %0, %1, %2;" : "=r"(h) : "f"(0.0f), "f"(f));
    const float fh = __uint_as_float(h << 16);
    asm("cvt.rn.bf16x2.f32 %0, %1, %2;" : "=r"(l) : "f"(0.0f), "f"(f - fh));
    return (h & 0xffffu) | (l << 16);
}
__device__ __forceinline__ float warp_sum(float v) {
    v += __shfl_xor_sync(0xffffffffu, v, 16);
    v += __shfl_xor_sync(0xffffffffu, v, 8);
    v += __shfl_xor_sync(0xffffffffu, v, 4);
    v += __shfl_xor_sync(0xffffffffu, v, 2);
    v += __shfl_xor_sync(0xffffffffu, v, 1);
    return v;
}

// ============================================================================
// G1: logits = x^T W^T + b (split-bf16, 3 terms) -> softmax over 64 -> packed S
//     + per-block wsum partials.
// grid (32, 16), 256 thr. Block: 128 tokens x 64 clusters, K=512 (8 chunks).
// ============================================================================
#define XHI 0
#define XLO 16384
#define WHI 32768
#define WLO 40960
#define BIASOF 49152
#define G1_SMEM 49408

__global__ __launch_bounds__(256, 2) void g1_softmax(
    const float* __restrict__ x, const float* __restrict__ Wc,
    const float* __restrict__ bc) {
    extern __shared__ char smem[];
    const uint32_t sb = smem_to_u32(smem);
    const int t = threadIdx.x, T = t & 31, w = t >> 5;
    const int b = blockIdx.y, n0 = blockIdx.x * 128;
    const float* xb = x + (size_t)b * (D_ * N_);
    if (t < 64) ((float*)(smem + BIASOF))[t] = bc[t];

    float acc[8][4];
#pragma unroll
    for (int j = 0; j < 8; j++)
#pragma unroll
        for (int i = 0; i < 4; i++) acc[j][i] = 0.0f;

    // ldmatrix lane components
    const int ak = ((T >> 4) & 1) * 8 + (T & 7);         // A: k(d) row offset
    const int am = (w * 16 + ((T >> 3) & 1) * 8) * 2;    // A: m(token) byte col
    const int bn = ((T >> 4) & 1) * 8 + (T & 7);         // B: n row offset
    const int bkb = ((T >> 3) & 1) * 16;                 // B: k byte col offset
    const int wcl = t >> 2;

    for (int c = 0; c < 8; c++) {
        const int d0 = c * 64;
        float4 xv[8];
#pragma unroll
        for (int i = 0; i < 8; i++)
            xv[i] = *(const float4*)(xb + (size_t)(d0 + i * 8 + w) * N_ + n0 + T * 4);
        float4 wv[4];
#pragma unroll
        for (int i = 0; i < 4; i++)
            wv[i] = *(const float4*)(Wc + (size_t)wcl * D_ + d0 + (t & 3) * 4 + i * 16);

        __syncthreads();   // prev chunk's ldmatrix complete
#pragma unroll
        for (int i = 0; i < 8; i++) {
            const int dd = i * 8 + w;
            const uint32_t col = (uint32_t)(T * 8) ^ (uint32_t)((dd & 7) << 4);
            uint32_t h0, l0, h1, l1;
            cvt_hilo(xv[i].x, xv[i].y, h0, l0);
            cvt_hilo(xv[i].z, xv[i].w, h1, l1);
            sts64(sb + XHI + dd * 256 + col, h0, h1);
            sts64(sb + XLO + dd * 256 + col, l0, l1);
        }
#pragma unroll
        for (int i = 0; i < 4; i++) {
            const uint32_t col =
                (uint32_t)((t & 3) * 8 + i * 32) ^ (uint32_t)((wcl & 7) << 4);
            uint32_t h0, l0, h1, l1;
            cvt_hilo(wv[i].x, wv[i].y, h0, l0);
            cvt_hilo(wv[i].z, wv[i].w, h1, l1);
            sts64(sb + WHI + wcl * 128 + col, h0, h1);
            sts64(sb + WLO + wcl * 128 + col, l0, l1);
        }
        __syncthreads();

#pragma unroll
        for (int ks = 0; ks < 4; ks++) {
            const int kd = ks * 16;
            const int arow = kd + ak;
            const uint32_t aaddr =
                sb + XHI + arow * 256 + ((uint32_t)am ^ (uint32_t)((arow & 7) << 4));
            uint32_t ah[4], al[4];
            ldsm4t(aaddr, ah);
            ldsm4t(aaddr + (XLO - XHI), al);
            uint32_t bh[4][4], bl[4][4];
#pragma unroll
            for (int g = 0; g < 4; g++) {
                const int brow = g * 16 + bn;
                const uint32_t baddr = sb + WHI + brow * 128 +
                    ((uint32_t)(kd * 2 + bkb) ^ (uint32_t)((brow & 7) << 4));
                ldsm4(baddr, bh[g]);
                ldsm4(baddr + (WLO - WHI), bl[g]);
            }
#pragma unroll
            for (int g = 0; g < 4; g++) {
                mma_bf16(acc[2 * g], ah, bh[g][0], bh[g][1]);
                mma_bf16(acc[2 * g + 1], ah, bh[g][2], bh[g][3]);
            }
#pragma unroll
            for (int g = 0; g < 4; g++) {
                mma_bf16(acc[2 * g], ah, bl[g][0], bl[g][1]);
                mma_bf16(acc[2 * g + 1], ah, bl[g][2], bl[g][3]);
            }
#pragma unroll
            for (int g = 0; g < 4; g++) {
                mma_bf16(acc[2 * g], al, bh[g][0], bh[g][1]);
                mma_bf16(acc[2 * g + 1], al, bh[g][2], bh[g][3]);
            }
        }
    }
    __syncthreads();

    // bias + softmax (rows r0 = w*16 + T/4, r1 = r0+8; quad holds full 64 cl)
    const float* bias = (const float*)(smem + BIASOF);
    float m0 = -3.0e38f, m1 = -3.0e38f;
#pragma unroll
    for (int j = 0; j < 8; j++) {
        const float bb0 = bias[j * 8 + (T & 3) * 2];
        const float bb1 = bias[j * 8 + (T & 3) * 2 + 1];
        acc[j][0] += bb0; acc[j][1] += bb1;
        acc[j][2] += bb0; acc[j][3] += bb1;
        m0 = fmaxf(m0, fmaxf(acc[j][0], acc[j][1]));
        m1 = fmaxf(m1, fmaxf(acc[j][2], acc[j][3]));
    }
    m0 = fmaxf(m0, __shfl_xor_sync(0xffffffffu, m0, 1));
    m0 = fmaxf(m0, __shfl_xor_sync(0xffffffffu, m0, 2));
    m1 = fmaxf(m1, __shfl_xor_sync(0xffffffffu, m1, 1));
    m1 = fmaxf(m1, __shfl_xor_sync(0xffffffffu, m1, 2));
    float s0 = 0.0f, s1 = 0.0f;
#pragma unroll
    for (int j = 0; j < 8; j++) {
        acc[j][0] = __expf(acc[j][0] - m0); s0 += acc[j][0];
        acc[j][1] = __expf(acc[j][1] - m0); s0 += acc[j][1];
        acc[j][2] = __expf(acc[j][2] - m1); s1 += acc[j][2];
        acc[j][3] = __expf(acc[j][3] - m1); s1 += acc[j][3];
    }
    s0 += __shfl_xor_sync(0xffffffffu, s0, 1);
    s0 += __shfl_xor_sync(0xffffffffu, s0, 2);
    s1 += __shfl_xor_sync(0xffffffffu, s1, 1);
    s1 += __shfl_xor_sync(0xffffffffu, s1, 2);
    const float inv0 = 1.0f / s0, inv1 = 1.0f / s1;

    uint32_t* Ts = (uint32_t*)smem;   // [64][132] padded
    const int tok0 = w * 16 + (T >> 2), tok1 = tok0 + 8;
#pragma unroll
    for (int j = 0; j < 8; j++) {
        const int cl = j * 8 + (T & 3) * 2;
        Ts[cl * 132 + tok0] = pack_hilo(acc[j][0] * inv0);
        Ts[(cl + 1) * 132 + tok0] = pack_hilo(acc[j][1] * inv0);
        Ts[cl * 132 + tok1] = pack_hilo(acc[j][2] * inv1);
        Ts[(cl + 1) * 132 + tok1] = pack_hilo(acc[j][3] * inv1);
    }
    __syncthreads();
    const int cl = t >> 2;
    uint32_t* Sg = g_Spk + (size_t)(b * 64 + cl) * N_ + n0;
    float wacc = 0.0f;
#pragma unroll
    for (int jj = 0; jj < 8; jj++) {
        const int colx = (t & 3) * 4 + jj * 16;
        uint4 v;
        v.x = Ts[cl * 132 + colx];     v.y = Ts[cl * 132 + colx + 1];
        v.z = Ts[cl * 132 + colx + 2]; v.w = Ts[cl * 132 + colx + 3];
        *(uint4*)(Sg + colx) = v;
        const uint32_t u[4] = {v.x, v.y, v.z, v.w};
#pragma unroll
        for (int q = 0; q < 4; q++) {
            wacc += __uint_as_float(u[q] << 16);
            wacc += __uint_as_float(u[q] & 0xffff0000u);
        }
    }
    // reduce the 4 threads owning this cluster -> wsum partial for this n-tile
    wacc += __shfl_xor_sync(0xffffffffu, wacc, 1);
    wacc += __shfl_xor_sync(0xffffffffu, wacc, 2);
    if ((t & 3) == 0)
        g_wsumP[((size_t)b * 32 + blockIdx.x) * K_ + cl] = wacc;
}

// ============================================================================
// G2: V[d,k] = sum_n x[d,n] * S[n,k] (split-bf16, 3 terms).
// grid (4 dtile, 16 b, 4 nsplit), 256 thr. Block: 128 d x 64 cl, K=1024 n.
// ============================================================================
#define AHI 0
#define ALO 16384
#define BHI 32768
#define BLO 40960
#define G2_SMEM 49152

__global__ __launch_bounds__(256, 2) void g2_wx(const float* __restrict__ x) {
    extern __shared__ char smem[];
    const uint32_t sb = smem_to_u32(smem);
    const int t = threadIdx.x, T = t & 31, w = t >> 5;
    const int d0 = blockIdx.x * 128, b = blockIdx.y, ns = blockIdx.z;
    const float* xb = x + (size_t)b * (D_ * N_);
    const uint32_t* Sb = g_Spk + (size_t)b * (K_ * N_);

    float acc[8][4];
#pragma unroll
    for (int j = 0; j < 8; j++)
#pragma unroll
        for (int i = 0; i < 4; i++) acc[j][i] = 0.0f;

    const int am8 = ((T >> 3) & 1) * 8;
    const int akb = ((T >> 4) & 1) * 16;
    const int bn = ((T >> 4) & 1) * 8 + (T & 7);
    const int bkb = ((T >> 3) & 1) * 16;
    const int scl = t >> 2;

    for (int ch = 0; ch < 16; ch++) {
        const int nb = ns * 1024 + ch * 64;
        float4 xv[8];
#pragma unroll
        for (int i = 0; i < 8; i++)
            xv[i] = *(const float4*)(xb + (size_t)(d0 + i * 16 + (t >> 4)) * N_ +
                                     nb + (t & 15) * 4);
        uint4 sv[4];
#pragma unroll
        for (int i = 0; i < 4; i++)
            sv[i] = *(const uint4*)(Sb + (size_t)scl * N_ + nb + (t & 3) * 4 + i * 16);

        __syncthreads();
#pragma unroll
        for (int i = 0; i < 8; i++) {
            const int dd = i * 16 + (t >> 4);
            const uint32_t col = (uint32_t)((t & 15) * 8) ^ (uint32_t)((dd & 7) << 4);
            uint32_t h0, l0, h1, l1;
            cvt_hilo(xv[i].x, xv[i].y, h0, l0);
            cvt_hilo(xv[i].z, xv[i].w, h1, l1);
            sts64(sb + AHI + dd * 128 + col, h0, h1);
            sts64(sb + ALO + dd * 128 + col, l0, l1);
        }
#pragma unroll
        for (int i = 0; i < 4; i++) {
            const uint32_t col =
                (uint32_t)((t & 3) * 8 + i * 32) ^ (uint32_t)((scl & 7) << 4);
            sts64(sb + BHI + scl * 128 + col,
                  __byte_perm(sv[i].x, sv[i].y, 0x5410),
                  __byte_perm(sv[i].z, sv[i].w, 0x5410));
            sts64(sb + BLO + scl * 128 + col,
                  __byte_perm(sv[i].x, sv[i].y, 0x7632),
                  __byte_perm(sv[i].z, sv[i].w, 0x7632));
        }
        __syncthreads();

#pragma unroll
        for (int ks = 0; ks < 4; ks++) {
            const int kd = ks * 16;
            const int arow = w * 16 + am8 + (T & 7);
            const uint32_t aaddr = sb + AHI + arow * 128 +
                ((uint32_t)(kd * 2 + akb) ^ (uint32_t)((arow & 7) << 4));
            uint32_t ah[4], al[4];
            ldsm4(aaddr, ah);
            ldsm4(aaddr + (ALO - AHI), al);
            uint32_t bh[4][4], bl[4][4];
#pragma unroll
            for (int g = 0; g < 4; g++) {
                const int brow = g * 16 + bn;
                const uint32_t baddr = sb + BHI + brow * 128 +
                    ((uint32_t)(kd * 2 + bkb) ^ (uint32_t)((brow & 7) << 4));
                ldsm4(baddr, bh[g]);
                ldsm4(baddr + (BLO - BHI), bl[g]);
            }
#pragma unroll
            for (int g = 0; g < 4; g++) {
                mma_bf16(acc[2 * g], ah, bh[g][0], bh[g][1]);
                mma_bf16(acc[2 * g + 1], ah, bh[g][2], bh[g][3]);
            }
#pragma unroll
            for (int g = 0; g < 4; g++) {
                mma_bf16(acc[2 * g], ah, bl[g][0], bl[g][1]);
                mma_bf16(acc[2 * g + 1], ah, bl[g][2], bl[g][3]);
            }
#pragma unroll
            for (int g = 0; g < 4; g++) {
                mma_bf16(acc[2 * g], al, bh[g][0], bh[g][1]);
                mma_bf16(acc[2 * g + 1], al, bh[g][2], bh[g][3]);
            }
        }
    }
    __syncthreads();

    // smem transpose -> coalesced [k][d] stores
    float* Vt = (float*)smem;   // [64][132] padded
    const int dd0 = w * 16 + (T >> 2), dd1 = dd0 + 8;
#pragma unroll
    for (int j = 0; j < 8; j++) {
        const int cl = j * 8 + (T & 3) * 2;
        Vt[cl * 132 + dd0] = acc[j][0];
        Vt[(cl + 1) * 132 + dd0] = acc[j][1];
        Vt[cl * 132 + dd1] = acc[j][2];
        Vt[(cl + 1) * 132 + dd1] = acc[j][3];
    }
    __syncthreads();
    float* Vp = g_Vp + (size_t)ns * (B_ * K_ * D_);
    const int cl = t >> 2;
    float* dst = Vp + (size_t)(b * 64 + cl) * D_ + d0;
#pragma unroll
    for (int jj = 0; jj < 8; jj++) {
        const int colx = (t & 3) * 4 + jj * 16;
        float4 v;
        v.x = Vt[cl * 132 + colx];     v.y = Vt[cl * 132 + colx + 1];
        v.z = Vt[cl * 132 + colx + 2]; v.w = Vt[cl * 132 + colx + 3];
        *(float4*)(dst + colx) = v;
    }
}

// ============================================================================
// norm1: vlad = sum(4 partials) - wsum*c, intra-L2-normalize, emit norm^2.
// wsum reduced from 32 per-tile partials (fixed shfl-tree order: deterministic).
// ============================================================================
__global__ __launch_bounds__(128) void k_norm1(
    const float* __restrict__ centers, float* __restrict__ out) {
    const int k = blockIdx.x, b = blockIdx.y, t = threadIdx.x;
    const size_t row = ((size_t)b * K_ + k) * D_;
    __shared__ float wsh;
    if (t < 32) {
        float p = g_wsumP[((size_t)b * 32 + t) * K_ + k];
        p = warp_sum(p);
        if (t == 0) wsh = p;
    }
    const float4 v0 = *(const float4*)(g_Vp + row + t * 4);
    const float4 v1 = *(const float4*)(g_Vp + (size_t)(B_ * K_ * D_) + row + t * 4);
    const float4 v2 = *(const float4*)(g_Vp + (size_t)2 * (B_ * K_ * D_) + row + t * 4);
    const float4 v3 = *(const float4*)(g_Vp + (size_t)3 * (B_ * K_ * D_) + row + t * 4);
    const float4 c = *(const float4*)(centers + k * D_ + t * 4);
    __syncthreads();
    const float ws = wsh;
    float4 val;
    val.x = ((v0.x + v1.x) + (v2.x + v3.x)) - ws * c.x;
    val.y = ((v0.y + v1.y) + (v2.y + v3.y)) - ws * c.y;
    val.z = ((v0.z + v1.z) + (v2.z + v3.z)) - ws * c.z;
    val.w = ((v0.w + v1.w) + (v2.w + v3.w)) - ws * c.w;
    float ss = val.x * val.x + val.y * val.y + val.z * val.z + val.w * val.w;
    ss = warp_sum(ss);
    __shared__ float sm[4];
    if ((t & 31) == 0) sm[t >> 5] = ss;
    __syncthreads();
    const float total = (sm[0] + sm[1]) + (sm[2] + sm[3]);
    const float inv = 1.0f / fmaxf(sqrtf(total), EPSV);
    val.x *= inv; val.y *= inv; val.z *= inv; val.w *= inv;
    *(float4*)(out + row + t * 4) = val;
    if (t == 0) g_rn[b * K_ + k] = total * inv * inv;
}

// ============================================================================
// finish: per-b global sumsq over 64 row-norms, then scale b's 32K outputs.
// Grid 16, 256 threads.
// ============================================================================
__global__ __launch_bounds__(256) void k_finish(float* __restrict__ out) {
    const int b = blockIdx.x, t = threadIdx.x;
    __shared__ float s2[2];
    __shared__ float invs;
    if (t < 64) {
        float v = g_rn[b * K_ + t];
        v += __shfl_xor_sync(0xffffffffu, v, 16);
        v += __shfl_xor_sync(0xffffffffu, v, 8);
        v += __shfl_xor_sync(0xffffffffu, v, 4);
        v += __shfl_xor_sync(0xffffffffu, v, 2);
        v += __shfl_xor_sync(0xffffffffu, v, 1);
        if ((t & 31) == 0) s2[t >> 5] = v;
    }
    __syncthreads();
    if (t == 0) invs = 1.0f / fmaxf(sqrtf(s2[0] + s2[1]), EPSV);
    __syncthreads();
    const float inv = invs;
    float* o = out + (size_t)b * (K_ * D_);
#pragma unroll
    for (int i = 0; i < 32; i++) {
        const int idx = (i * 256 + t) * 4;
        float4 v = *(float4*)(o + idx);
        v.x *= inv; v.y *= inv; v.z *= inv; v.w *= inv;
        *(float4*)(o + idx) = v;
    }
}

// ============================================================================
extern "C" void kernel_launch(void* const* d_in, const int* in_sizes, int n_in,
                              void* d_out, int out_size) {
    const float* x = (const float*)d_in[0];
    const float* conv_w = (const float*)d_in[1];
    const float* conv_b = (const float*)d_in[2];
    const float* centers = (const float*)d_in[3];
    float* out = (float*)d_out;

    cudaFuncSetAttribute(g1_softmax, cudaFuncAttributeMaxDynamicSharedMemorySize, G1_SMEM);
    cudaFuncSetAttribute(g2_wx, cudaFuncAttributeMaxDynamicSharedMemorySize, G2_SMEM);

    g1_softmax<<<dim3(32, 16), 256, G1_SMEM>>>(x, conv_w, conv_b);
    g2_wx<<<dim3(4, 16, 4), 256, G2_SMEM>>>(x);
    k_norm1<<<dim3(64, 16), 128>>>(centers, out);
    k_finish<<<16, 256>>>(out);
}